// round 8
// baseline (speedup 1.0000x reference)
#include <cuda_runtime.h>
#include <cuda_bf16.h>
#include <cstdint>

#define M_TOT 4096
#define N_TOT 11008
#define K_TOT 4096
#define QWC   1376
#define NGRP  32

#define BM 128
#define BN 128
#define BK 128
#define NCH 32
#define THREADS 320       // 8 consumer warps + 2 producer warps
#define NSTAGE 3

#define STG_BYTES 49152   // A1 16K + A2 16K + B 16K
#define OFF_A1 0
#define OFF_A2 16384
#define OFF_B  32768
#define OFF_BAR 0
#define OFF_STG 1024
#define OFF_SA (OFF_STG + NSTAGE * STG_BYTES)   // 148480 (3 x 512B)
#define OFF_SC (OFF_SA + NSTAGE * 512)          // 150016
#define SMEM_TOTAL (OFF_SC + 16384)             // 166400

// quantized-A scratch
__device__ int8_t q1G[(size_t)M_TOT * K_TOT];
__device__ int8_t q2G[(size_t)M_TOT * K_TOT];
__device__ float  sAG[(size_t)NGRP * M_TOT];

__device__ __forceinline__ uint32_t smem_u32(const void* p) {
    uint32_t a;
    asm("{ .reg .u64 t; cvta.to.shared.u64 t, %1; cvt.u32.u64 %0, t; }"
        : "=r"(a) : "l"(p));
    return a;
}
__device__ __forceinline__ void ldsm4(uint32_t* r, uint32_t addr) {
    asm volatile("ldmatrix.sync.aligned.m8n8.x4.shared.b16 {%0,%1,%2,%3}, [%4];"
                 : "=r"(r[0]), "=r"(r[1]), "=r"(r[2]), "=r"(r[3]) : "r"(addr));
}
__device__ __forceinline__ void mma_s8(int* d, const uint32_t* a, const uint32_t* b) {
    asm volatile(
        "mma.sync.aligned.m16n8k32.row.col.s32.s8.s8.s32 "
        "{%0,%1,%2,%3}, {%4,%5,%6,%7}, {%8,%9}, {%0,%1,%2,%3};"
        : "+r"(d[0]), "+r"(d[1]), "+r"(d[2]), "+r"(d[3])
        : "r"(a[0]), "r"(a[1]), "r"(a[2]), "r"(a[3]), "r"(b[0]), "r"(b[1]));
}
__device__ __forceinline__ void mbar_init(uint32_t m, uint32_t c) {
    asm volatile("mbarrier.init.shared.b64 [%0], %1;" :: "r"(m), "r"(c) : "memory");
}
__device__ __forceinline__ void mbar_arrive(uint32_t m) {
    asm volatile("mbarrier.arrive.shared.b64 _, [%0];" :: "r"(m) : "memory");
}
__device__ __forceinline__ void mbar_wait(uint32_t m, uint32_t parity) {
    uint32_t done;
    asm volatile(
        "{\n\t.reg .pred p;\n\t"
        "mbarrier.try_wait.parity.acquire.cta.shared::cta.b64 p, [%1], %2;\n\t"
        "selp.b32 %0, 1, 0, p;\n\t}"
        : "=r"(done) : "r"(m), "r"(parity) : "memory");
    if (!done) {
        asm volatile(
            "{\n\t.reg .pred P1;\n\t"
            "WL_%=:\n\t"
            "mbarrier.try_wait.parity.acquire.cta.shared::cta.b64 P1, [%0], %1, 0x989680;\n\t"
            "@P1 bra.uni WD_%=;\n\t"
            "bra.uni WL_%=;\n\t"
            "WD_%=:\n\t}"
            :: "r"(m), "r"(parity) : "memory");
    }
}

// ================= A quantization prepass =================
// warp <-> (row m, group g): a = sA*(128*q1 + q2), sA = max|a|/16256
__global__ void __launch_bounds__(256) quant_kernel(const float* __restrict__ A) {
    const int widx = (blockIdx.x * 256 + threadIdx.x) >> 5;
    const int lane = threadIdx.x & 31;
    const int m = widx >> 5;
    const int g = widx & 31;
    const float4 v = *reinterpret_cast<const float4*>(
        A + (size_t)m * K_TOT + g * 128 + lane * 4);
    float ax = fmaxf(fmaxf(fabsf(v.x), fabsf(v.y)), fmaxf(fabsf(v.z), fabsf(v.w)));
    #pragma unroll
    for (int o = 16; o; o >>= 1) ax = fmaxf(ax, __shfl_xor_sync(0xffffffffu, ax, o));
    const float inv = ax > 0.f ? 16256.f / ax : 0.f;
    float f[4] = {v.x, v.y, v.z, v.w};
    int p1 = 0, p2 = 0;
    #pragma unroll
    for (int j = 0; j < 4; j++) {
        const float u = f[j] * inv;
        const int a1 = __float2int_rn(u * 0.0078125f);
        const int a2 = __float2int_rn(fmaf((float)a1, -128.f, u));
        p1 |= (a1 & 255) << (8 * j);
        p2 |= (a2 & 255) << (8 * j);
    }
    const size_t wi = ((size_t)m * K_TOT + g * 128) / 4 + lane;
    reinterpret_cast<int*>(q1G)[wi] = p1;
    reinterpret_cast<int*>(q2G)[wi] = p2;
    if (lane == 0) sAG[(size_t)g * M_TOT + m] = ax * (1.f / 16256.f);
}

// ================= fused dequant GEMM =================
__global__ void __launch_bounds__(THREADS, 1) gemm_i8_kernel(
    const unsigned* __restrict__ QW, const unsigned* __restrict__ QZ,
    const float* __restrict__ SC, float* __restrict__ C)
{
    extern __shared__ char smem[];
    const uint32_t sbase = smem_u32(smem);
    const int tid  = threadIdx.x;
    const int wid  = tid >> 5;
    const int lane = tid & 31;
    const int bm = blockIdx.y * BM;
    const int bn = blockIdx.x * BN;
    float* scS = (float*)(smem + OFF_SC);

    if (tid == 0) {
        #pragma unroll
        for (int s = 0; s < NSTAGE; s++) {
            mbar_init(sbase + OFF_BAR + 16 * s, 64);       // full: producer threads
            mbar_init(sbase + OFF_BAR + 16 * s + 8, 256);  // empty: consumer threads
        }
    }
    for (int idx = tid; idx < 1024; idx += THREADS) {
        const int g = idx >> 5, v = idx & 31;
        *reinterpret_cast<float4*>(scS + g * 128 + v * 4) =
            *reinterpret_cast<const float4*>(SC + (size_t)g * N_TOT + bn + v * 4);
    }
    __syncthreads();

    if (wid >= 8) {
        // =============== PRODUCER (warps 8-9, 64 threads) ===============
        const int ptid = tid - 256;
        int pe[NSTAGE] = {1, 1, 1};
        for (int it = 0; it < NCH; ++it) {
            const int s = it % NSTAGE;
            mbar_wait(sbase + OFF_BAR + 16 * s + 8, pe[s]);
            pe[s] ^= 1;
            const int k0 = it * BK;
            char* stg = smem + OFF_STG + s * STG_BYTES;

            // A q1/q2 tiles: 128 rows x 128 k s8, 16B chunks, XOR swizzle
            #pragma unroll
            for (int r = 0; r < 16; r++) {
                const int idx = ptid + r * 64;       // 0..1023
                const int m = idx >> 3, c = idx & 7;
                const int4 v1 = *reinterpret_cast<const int4*>(
                    &q1G[(size_t)(bm + m) * K_TOT + k0 + c * 16]);
                const int4 v2 = *reinterpret_cast<const int4*>(
                    &q2G[(size_t)(bm + m) * K_TOT + k0 + c * 16]);
                const int off = m * 128 + ((c ^ (m & 7)) << 4);
                *reinterpret_cast<int4*>(stg + OFF_A1 + off) = v1;
                *reinterpret_cast<int4*>(stg + OFF_A2 + off) = v2;
            }
            // sA for this group
            #pragma unroll
            for (int r = 0; r < 2; r++) {
                const int m = ptid + r * 64;
                ((float*)(smem + OFF_SA + s * 512))[m] = sAG[(size_t)it * M_TOT + bm + m];
            }
            // B: dequant nibbles -> s8, [n][k] rows of 128B, swizzled
            #pragma unroll
            for (int blk = 0; blk < 8; blk++) {
                const int idx = ptid + blk * 64;     // 0..511
                const int w  = idx & 15;             // n-octet
                const int kq = idx >> 4;             // 0..31 k-quad
                const int col = (bn >> 3) + w;
                const unsigned qz = QZ[(size_t)it * QWC + col];
                const unsigned z0 = qz & 0x0F0F0F0Fu, z1 = (qz >> 4) & 0x0F0F0F0Fu;
                const unsigned zc0 = 0x80808080u - z0, zc1 = 0x80808080u - z1;
                unsigned e[4], o[4];
                #pragma unroll
                for (int j = 0; j < 4; j++) {
                    const unsigned q = QW[(size_t)(k0 + kq * 4 + j) * QWC + col];
                    e[j] = ((q & 0x0F0F0F0Fu) + zc0) ^ 0x80808080u;
                    o[j] = (((q >> 4) & 0x0F0F0F0Fu) + zc1) ^ 0x80808080u;
                }
                unsigned t[8];
                unsigned lo01 = __byte_perm(e[0], e[1], 0x5140);
                unsigned hi01 = __byte_perm(e[0], e[1], 0x7362);
                unsigned lo23 = __byte_perm(e[2], e[3], 0x5140);
                unsigned hi23 = __byte_perm(e[2], e[3], 0x7362);
                t[0] = __byte_perm(lo01, lo23, 0x5410);
                t[2] = __byte_perm(lo01, lo23, 0x7632);
                t[4] = __byte_perm(hi01, hi23, 0x5410);
                t[6] = __byte_perm(hi01, hi23, 0x7632);
                lo01 = __byte_perm(o[0], o[1], 0x5140);
                hi01 = __byte_perm(o[0], o[1], 0x7362);
                lo23 = __byte_perm(o[2], o[3], 0x5140);
                hi23 = __byte_perm(o[2], o[3], 0x7362);
                t[1] = __byte_perm(lo01, lo23, 0x5410);
                t[3] = __byte_perm(lo01, lo23, 0x7632);
                t[5] = __byte_perm(hi01, hi23, 0x5410);
                t[7] = __byte_perm(hi01, hi23, 0x7632);
                const int chunk = kq >> 2;
                const int wb = (kq & 3) * 4;
                #pragma unroll
                for (int d = 0; d < 8; d++) {
                    const int n = w * 8 + d;
                    const int cs = chunk ^ (n & 7) ^ ((n >> 3) & 7);
                    *reinterpret_cast<unsigned*>(stg + OFF_B + n * 128 + (cs << 4) + wb) = t[d];
                }
            }
            mbar_arrive(sbase + OFF_BAR + 16 * s);
        }
    } else {
        // =============== CONSUMER (warps 0-7, 256 threads) ===============
        const int wm = (wid & 1) * 64;
        const int wn = (wid >> 1) * 32;
        const int rsel = ((lane >> 3) & 1) * 8 + (lane & 7);
        const int hi8  = lane >> 4;
        const int l7   = lane & 7;
        int cf[NSTAGE] = {0, 0, 0};

        float accF[4][4][4];
        #pragma unroll
        for (int i = 0; i < 4; i++)
            #pragma unroll
            for (int j = 0; j < 4; j++)
                #pragma unroll
                for (int e = 0; e < 4; e++) accF[i][j][e] = 0.f;

        for (int it = 0; it < NCH; ++it) {
            const int s = it % NSTAGE;
            mbar_wait(sbase + OFF_BAR + 16 * s, cf[s]);
            cf[s] ^= 1;
            const uint32_t base = sbase + OFF_STG + s * STG_BYTES;

            float sa0[4], sa1[4];
            {
                const float* saP = (const float*)(smem + OFF_SA + s * 512);
                #pragma unroll
                for (int mi = 0; mi < 4; mi++) {
                    const int r = wm + mi * 16 + (lane >> 2);
                    sa0[mi] = saP[r];
                    sa1[mi] = saP[r + 8];
                }
            }
            float sc0[4], sc1[4];
            #pragma unroll
            for (int nj = 0; nj < 4; nj++) {
                const float* p = scS + it * 128 + wn + nj * 8 + (lane & 3) * 2;
                sc0[nj] = p[0];
                sc1[nj] = p[1];
            }

            #pragma unroll
            for (int pass = 0; pass < 2; pass++) {
                int D[4][4][4];
                #pragma unroll
                for (int i = 0; i < 4; i++)
                    #pragma unroll
                    for (int j = 0; j < 4; j++)
                        #pragma unroll
                        for (int e = 0; e < 4; e++) D[i][j][e] = 0;

                const uint32_t aBase = base + (pass ? OFF_A2 : OFF_A1);
                #pragma unroll
                for (int ks = 0; ks < 4; ks++) {
                    uint32_t bq[4][2];
                    #pragma unroll
                    for (int pr = 0; pr < 2; pr++) {
                        const int n = wn + pr * 16 + ((lane >> 4) << 3) + l7;
                        const int chunk = 2 * ks + ((lane >> 3) & 1);
                        const int cs = chunk ^ (n & 7) ^ ((n >> 3) & 7);
                        uint32_t t[4];
                        ldsm4(t, base + OFF_B + n * 128 + (cs << 4));
                        bq[pr * 2][0] = t[0]; bq[pr * 2][1] = t[1];
                        bq[pr * 2 + 1][0] = t[2]; bq[pr * 2 + 1][1] = t[3];
                    }
                    #pragma unroll
                    for (int mi = 0; mi < 4; mi++) {
                        const int m = wm + mi * 16 + rsel;
                        const int aoff = m * 128 + (((2 * ks + hi8) ^ (m & 7)) << 4);
                        uint32_t a[4];
                        ldsm4(a, aBase + aoff);
                        #pragma unroll
                        for (int nj = 0; nj < 4; nj++) mma_s8(D[mi][nj], a, bq[nj]);
                    }
                }
                if (pass == 1) mbar_arrive(sbase + OFF_BAR + 16 * s + 8);

                const float pmul = pass ? 1.f : 128.f;
                #pragma unroll
                for (int mi = 0; mi < 4; mi++) {
                    const float pm0 = sa0[mi] * pmul;
                    const float pm1 = sa1[mi] * pmul;
                    #pragma unroll
                    for (int nj = 0; nj < 4; nj++) {
                        const float s00 = pm0 * sc0[nj], s01 = pm0 * sc1[nj];
                        const float s10 = pm1 * sc0[nj], s11 = pm1 * sc1[nj];
                        accF[mi][nj][0] = fmaf(s00, (float)D[mi][nj][0], accF[mi][nj][0]);
                        accF[mi][nj][1] = fmaf(s01, (float)D[mi][nj][1], accF[mi][nj][1]);
                        accF[mi][nj][2] = fmaf(s10, (float)D[mi][nj][2], accF[mi][nj][2]);
                        accF[mi][nj][3] = fmaf(s11, (float)D[mi][nj][3], accF[mi][nj][3]);
                    }
                }
            }
        }

        // epilogue
        #pragma unroll
        for (int mi = 0; mi < 4; mi++)
            #pragma unroll
            for (int nj = 0; nj < 4; nj++) {
                const float* a = accF[mi][nj];
                const int row = bm + wm + mi * 16 + (lane >> 2);
                const int col = bn + wn + nj * 8 + (lane & 3) * 2;
                *reinterpret_cast<float2*>(&C[(size_t)row * N_TOT + col]) =
                    make_float2(a[0], a[1]);
                *reinterpret_cast<float2*>(&C[(size_t)(row + 8) * N_TOT + col]) =
                    make_float2(a[2], a[3]);
            }
    }
}

extern "C" void kernel_launch(void* const* d_in, const int* in_sizes, int n_in,
                              void* d_out, int out_size)
{
    const float*    A  = (const float*)d_in[0];
    const unsigned* QW = (const unsigned*)d_in[1];
    const unsigned* QZ = (const unsigned*)d_in[2];
    const float*    SC = (const float*)d_in[3];
    float*          C  = (float*)d_out;

    quant_kernel<<<M_TOT * NGRP / 8, 256>>>(A);

    cudaFuncSetAttribute(gemm_i8_kernel,
                         cudaFuncAttributeMaxDynamicSharedMemorySize, SMEM_TOTAL);
    dim3 grid(N_TOT / BN, M_TOT / BM);   // (86, 32)
    gemm_i8_kernel<<<grid, THREADS, SMEM_TOTAL>>>(QW, QZ, SC, C);
}

// round 9
// speedup vs baseline: 2.9536x; 2.9536x over previous
#include <cuda_runtime.h>
#include <cuda_bf16.h>
#include <cstdint>

#define M_TOT 4096
#define N_TOT 11008
#define K_TOT 4096
#define QWC   1376            // N_TOT/8 packed words per k-row

#define BM 128
#define BN 128
#define BK 64
#define NCH (K_TOT / BK)      // 64
#define THREADS 384           // 8 consumer warps + 4 producer warps
#define NSTAGE 4

// per-stage layout
#define STG_BYTES 49152
#define OFF_AH 0
#define OFF_AL 16384
#define OFF_B  32768
// smem map
#define OFF_BAR 0
#define OFF_STG 1024
#define OFF_SC  (OFF_STG + NSTAGE * STG_BYTES)      // 197632
#define SMEM_TOTAL (OFF_SC + 16384)                 // 214016

// bf16 bias: 0x4300 = 128.0, ulp = 1 -> (0x4300|nib) == 128 + nib exactly
#define BIAS2 0x43004300u

// prepass scratch: A split into bf16 hi/lo, [M][K] row-major
__device__ __nv_bfloat16 AhG[(size_t)M_TOT * K_TOT];
__device__ __nv_bfloat16 AlG[(size_t)M_TOT * K_TOT];

__device__ __forceinline__ uint32_t smem_u32(const void* p) {
    uint32_t a;
    asm("{ .reg .u64 t; cvta.to.shared.u64 t, %1; cvt.u32.u64 %0, t; }"
        : "=r"(a) : "l"(p));
    return a;
}
__device__ __forceinline__ void ldsm4(uint32_t* r, uint32_t addr) {
    asm volatile("ldmatrix.sync.aligned.m8n8.x4.shared.b16 {%0,%1,%2,%3}, [%4];"
                 : "=r"(r[0]), "=r"(r[1]), "=r"(r[2]), "=r"(r[3]) : "r"(addr));
}
__device__ __forceinline__ void ldsm4t(uint32_t* r, uint32_t addr) {
    asm volatile("ldmatrix.sync.aligned.m8n8.x4.trans.shared.b16 {%0,%1,%2,%3}, [%4];"
                 : "=r"(r[0]), "=r"(r[1]), "=r"(r[2]), "=r"(r[3]) : "r"(addr));
}
__device__ __forceinline__ void mma_bf16(float* d, const uint32_t* a, const uint32_t* b) {
    asm volatile(
        "mma.sync.aligned.m16n8k16.row.col.f32.bf16.bf16.f32 "
        "{%0,%1,%2,%3}, {%4,%5,%6,%7}, {%8,%9}, {%0,%1,%2,%3};"
        : "+f"(d[0]), "+f"(d[1]), "+f"(d[2]), "+f"(d[3])
        : "r"(a[0]), "r"(a[1]), "r"(a[2]), "r"(a[3]), "r"(b[0]), "r"(b[1]));
}
__device__ __forceinline__ void mbar_init(uint32_t m, uint32_t c) {
    asm volatile("mbarrier.init.shared.b64 [%0], %1;" :: "r"(m), "r"(c) : "memory");
}
__device__ __forceinline__ void mbar_arrive(uint32_t m) {
    asm volatile("mbarrier.arrive.shared.b64 _, [%0];" :: "r"(m) : "memory");
}
__device__ __forceinline__ void mbar_wait(uint32_t m, uint32_t parity) {
    uint32_t done;
    asm volatile(
        "{\n\t.reg .pred p;\n\t"
        "mbarrier.try_wait.parity.acquire.cta.shared::cta.b64 p, [%1], %2;\n\t"
        "selp.b32 %0, 1, 0, p;\n\t}"
        : "=r"(done) : "r"(m), "r"(parity) : "memory");
    if (!done) {
        asm volatile(
            "{\n\t.reg .pred P1;\n\t"
            "WL_%=:\n\t"
            "mbarrier.try_wait.parity.acquire.cta.shared::cta.b64 P1, [%0], %1, 0x989680;\n\t"
            "@P1 bra.uni WD_%=;\n\t"
            "bra.uni WL_%=;\n\t"
            "WD_%=:\n\t}"
            :: "r"(m), "r"(parity) : "memory");
    }
}
__device__ __forceinline__ void cp_async16(uint32_t dst, const void* src) {
    asm volatile("cp.async.cg.shared.global [%0], [%1], 16;"
                 :: "r"(dst), "l"(src) : "memory");
}

// ================= A split prepass: fp32 -> bf16 hi + bf16 lo =================
__global__ void __launch_bounds__(256) splitA_kernel(const float* __restrict__ A) {
    const size_t base = ((size_t)blockIdx.x * 256 + threadIdx.x) * 8;
    const float4 v0 = *reinterpret_cast<const float4*>(A + base);
    const float4 v1 = *reinterpret_cast<const float4*>(A + base + 4);
    __nv_bfloat162 h0 = __floats2bfloat162_rn(v0.x, v0.y);
    __nv_bfloat162 h1 = __floats2bfloat162_rn(v0.z, v0.w);
    __nv_bfloat162 h2 = __floats2bfloat162_rn(v1.x, v1.y);
    __nv_bfloat162 h3 = __floats2bfloat162_rn(v1.z, v1.w);
    __nv_bfloat162 l0 = __floats2bfloat162_rn(v0.x - __bfloat162float(h0.x),
                                              v0.y - __bfloat162float(h0.y));
    __nv_bfloat162 l1 = __floats2bfloat162_rn(v0.z - __bfloat162float(h1.x),
                                              v0.w - __bfloat162float(h1.y));
    __nv_bfloat162 l2 = __floats2bfloat162_rn(v1.x - __bfloat162float(h2.x),
                                              v1.y - __bfloat162float(h2.y));
    __nv_bfloat162 l3 = __floats2bfloat162_rn(v1.z - __bfloat162float(h3.x),
                                              v1.w - __bfloat162float(h3.y));
    *reinterpret_cast<uint4*>(AhG + base) =
        make_uint4(*(uint32_t*)&h0, *(uint32_t*)&h1, *(uint32_t*)&h2, *(uint32_t*)&h3);
    *reinterpret_cast<uint4*>(AlG + base) =
        make_uint4(*(uint32_t*)&l0, *(uint32_t*)&l1, *(uint32_t*)&l2, *(uint32_t*)&l3);
}

// ================= warp-specialized fused GEMM =================
__global__ void __launch_bounds__(THREADS, 1) gemm_ws_kernel(
    const unsigned* __restrict__ QW, const unsigned* __restrict__ QZ,
    const float* __restrict__ SC, float* __restrict__ C)
{
    extern __shared__ char smem[];
    const uint32_t sbase = smem_u32(smem);
    const int tid  = threadIdx.x;
    const int wid  = tid >> 5;
    const int lane = tid & 31;
    const int bm = blockIdx.y * BM;
    const int bn = blockIdx.x * BN;
    float* scS = (float*)(smem + OFF_SC);

    if (tid == 0) {
        #pragma unroll
        for (int s = 0; s < NSTAGE; s++) {
            mbar_init(sbase + OFF_BAR + 16 * s, 128);      // full: producer threads
            mbar_init(sbase + OFF_BAR + 16 * s + 8, 256);  // empty: consumer threads
        }
    }
    // stage scales (32 groups x 128 n = 1024 float4)
    for (int idx = tid; idx < 1024; idx += THREADS) {
        const int g = idx >> 5, v = idx & 31;
        *reinterpret_cast<float4*>(scS + g * 128 + v * 4) =
            *reinterpret_cast<const float4*>(SC + (size_t)g * N_TOT + bn + v * 4);
    }
    __syncthreads();

    if (wid >= 8) {
        // ========== PRODUCER (warps 8-11, 128 threads) ==========
        const int ptid = tid - 256;
        const int bw  = ptid & 15;     // B n-octet / packed-word
        const int bkb = ptid >> 4;     // B k base 0..7 (+8*r)
        int pe[NSTAGE] = {1, 1, 1, 1};

        for (int it = 0; it < NCH; ++it) {
            const int s = it % NSTAGE;
            mbar_wait(sbase + OFF_BAR + 16 * s + 8, pe[s]);
            pe[s] ^= 1;
            const int k0 = it * BK;
            char* stg = smem + OFF_STG + s * STG_BYTES;
            const uint32_t stgu = sbase + OFF_STG + s * STG_BYTES;

            // ---- A: cp.async bf16 hi/lo straight into swizzled slots ----
            #pragma unroll
            for (int r = 0; r < 16; r++) {
                const int idx = ptid + r * 128;     // 0..2047
                const int buf = idx >> 10;          // 0 = hi, 1 = lo
                const int mc  = idx & 1023;
                const int m = mc >> 3, c = mc & 7;
                const __nv_bfloat16* src =
                    (buf ? AlG : AhG) + (size_t)(bm + m) * K_TOT + k0 + c * 8;
                const uint32_t dst = stgu + (buf ? OFF_AL : OFF_AH)
                                   + m * 128 + ((c ^ (m & 7)) << 4);
                cp_async16(dst, src);
            }
            asm volatile("cp.async.commit_group;" ::: "memory");

            // ---- B: exact q = nib - zp in bf16 via 0x4300-bias + hsub2 ----
            const unsigned qz = QZ[(size_t)(it >> 1) * QWC + (bn >> 3) + bw];
            unsigned qw[8];
            #pragma unroll
            for (int r = 0; r < 8; r++)
                qw[r] = QW[(size_t)(k0 + bkb + 8 * r) * QWC + (bn >> 3) + bw];
            uint32_t zz[4];
            #pragma unroll
            for (int p = 0; p < 4; p++) {
                const unsigned zq = qz >> (8 * p);
                zz[p] = BIAS2 | (zq & 0xFu) | ((zq & 0xF0u) << 12);
            }
            #pragma unroll
            for (int r = 0; r < 8; r++) {
                const int k = bkb + 8 * r;
                const unsigned q = qw[r];
                uint32_t w[4];
                #pragma unroll
                for (int p = 0; p < 4; p++) {
                    const unsigned qq = q >> (8 * p);
                    uint32_t u = BIAS2 | (qq & 0xFu) | ((qq & 0xF0u) << 12);
                    __nv_bfloat162 d = __hsub2(*reinterpret_cast<__nv_bfloat162*>(&u),
                                               *reinterpret_cast<__nv_bfloat162*>(&zz[p]));
                    w[p] = *reinterpret_cast<uint32_t*>(&d);
                }
                const int off = k * 256 + ((bw ^ (k & 7)) << 4);
                *reinterpret_cast<uint4*>(stg + OFF_B + off) =
                    make_uint4(w[0], w[1], w[2], w[3]);
            }
            asm volatile("cp.async.wait_group 0;" ::: "memory");
            mbar_arrive(sbase + OFF_BAR + 16 * s);   // full (release)
        }
    } else {
        // ========== CONSUMER (warps 0-7, 256 threads) ==========
        const int wm = (wid & 1) * 64;
        const int wn = (wid >> 1) * 32;
        const int rsel = ((lane >> 3) & 1) * 8 + (lane & 7);
        const int hi8  = lane >> 4;
        const int l7   = lane & 7;
        int cf[NSTAGE] = {0, 0, 0, 0};

        float accF[4][4][4], accG[4][4][4];
        #pragma unroll
        for (int i = 0; i < 4; i++)
            #pragma unroll
            for (int j = 0; j < 4; j++)
                #pragma unroll
                for (int e = 0; e < 4; e++) { accF[i][j][e] = 0.f; accG[i][j][e] = 0.f; }

        for (int it = 0; it < NCH; ++it) {
            const int s = it % NSTAGE;
            mbar_wait(sbase + OFF_BAR + 16 * s, cf[s]);
            cf[s] ^= 1;

            const uint32_t base = sbase + OFF_STG + s * STG_BYTES;
            #pragma unroll
            for (int ks = 0; ks < 4; ks++) {
                uint32_t bq[4][2];
                const int krow = ks * 16 + rsel;
                #pragma unroll
                for (int pr = 0; pr < 2; pr++) {
                    const int ch = (wn >> 3) + pr * 2 + hi8;
                    const int off = krow * 256 + ((ch ^ l7) << 4);
                    uint32_t t[4];
                    ldsm4t(t, base + OFF_B + off);
                    bq[pr*2][0]=t[0]; bq[pr*2][1]=t[1];
                    bq[pr*2+1][0]=t[2]; bq[pr*2+1][1]=t[3];
                }
                #pragma unroll
                for (int mi = 0; mi < 4; mi++) {
                    const int m = wm + mi * 16 + rsel;
                    const int aoff = m * 128 + (((ks * 2 + hi8) ^ l7) << 4);
                    uint32_t ah[4];
                    ldsm4(ah, base + OFF_AH + aoff);
                    #pragma unroll
                    for (int nj = 0; nj < 4; nj++) mma_bf16(accG[mi][nj], ah, bq[nj]);
                    uint32_t al[4];
                    ldsm4(al, base + OFF_AL + aoff);
                    #pragma unroll
                    for (int nj = 0; nj < 4; nj++) mma_bf16(accG[mi][nj], al, bq[nj]);
                }
            }
            mbar_arrive(sbase + OFF_BAR + 16 * s + 8);   // empty

            if (it & 1) {
                const int g = it >> 1;
                #pragma unroll
                for (int nj = 0; nj < 4; nj++) {
                    const float2 s2 = *reinterpret_cast<const float2*>(
                        scS + g * 128 + wn + nj * 8 + (lane & 3) * 2);
                    #pragma unroll
                    for (int mi = 0; mi < 4; mi++) {
                        accF[mi][nj][0] = fmaf(s2.x, accG[mi][nj][0], accF[mi][nj][0]);
                        accF[mi][nj][1] = fmaf(s2.y, accG[mi][nj][1], accF[mi][nj][1]);
                        accF[mi][nj][2] = fmaf(s2.x, accG[mi][nj][2], accF[mi][nj][2]);
                        accF[mi][nj][3] = fmaf(s2.y, accG[mi][nj][3], accF[mi][nj][3]);
                        accG[mi][nj][0] = 0.f; accG[mi][nj][1] = 0.f;
                        accG[mi][nj][2] = 0.f; accG[mi][nj][3] = 0.f;
                    }
                }
            }
        }

        // epilogue
        #pragma unroll
        for (int mi = 0; mi < 4; mi++)
            #pragma unroll
            for (int nj = 0; nj < 4; nj++) {
                const float* a = accF[mi][nj];
                const int row = bm + wm + mi * 16 + (lane >> 2);
                const int col = bn + wn + nj * 8 + (lane & 3) * 2;
                *reinterpret_cast<float2*>(&C[(size_t)row * N_TOT + col]) =
                    make_float2(a[0], a[1]);
                *reinterpret_cast<float2*>(&C[(size_t)(row + 8) * N_TOT + col]) =
                    make_float2(a[2], a[3]);
            }
    }
}

extern "C" void kernel_launch(void* const* d_in, const int* in_sizes, int n_in,
                              void* d_out, int out_size)
{
    const float*    A  = (const float*)d_in[0];
    const unsigned* QW = (const unsigned*)d_in[1];
    const unsigned* QZ = (const unsigned*)d_in[2];
    const float*    SC = (const float*)d_in[3];
    float*          C  = (float*)d_out;

    splitA_kernel<<<(M_TOT * K_TOT) / (256 * 8), 256>>>(A);

    cudaFuncSetAttribute(gemm_ws_kernel,
                         cudaFuncAttributeMaxDynamicSharedMemorySize, SMEM_TOTAL);
    dim3 grid(N_TOT / BN, M_TOT / BM);   // (86, 32)
    gemm_ws_kernel<<<grid, THREADS, SMEM_TOTAL>>>(QW, QZ, SC, C);
}

// round 10
// speedup vs baseline: 4.8399x; 1.6386x over previous
#include <cuda_runtime.h>
#include <cuda_fp16.h>
#include <cstdint>

#define M_TOT 4096
#define N_TOT 11008
#define K_TOT 4096
#define QWC   1376            // N_TOT/8 packed words per k-row

#define BM 128
#define BN 128
#define BK 64
#define NCH (K_TOT / BK)      // 64
#define THREADS 256           // 4 consumer warps + 4 producer warps
#define NSTAGE 5

// per-stage layout: A 16KB + B 16KB
#define STG_BYTES 32768
#define OFF_A 0
#define OFF_B 16384
// smem map
#define OFF_BAR 0
#define OFF_STG 1024
#define OFF_SC  (OFF_STG + NSTAGE * STG_BYTES)      // 164864 (fp16 scales, 8KB)
#define SMEM_TOTAL (OFF_SC + 8192)                  // 173056

// fp16 bias: 0x6400 = 1024.0, ulp = 1 -> (0x6400|nib) == 1024 + nib exactly
#define BIAS2 0x64006400u

// prepass scratch: A as fp16, [M][K] row-major
__device__ __half AhG[(size_t)M_TOT * K_TOT];

__device__ __forceinline__ uint32_t smem_u32(const void* p) {
    uint32_t a;
    asm("{ .reg .u64 t; cvta.to.shared.u64 t, %1; cvt.u32.u64 %0, t; }"
        : "=r"(a) : "l"(p));
    return a;
}
__device__ __forceinline__ void ldsm4(uint32_t* r, uint32_t addr) {
    asm volatile("ldmatrix.sync.aligned.m8n8.x4.shared.b16 {%0,%1,%2,%3}, [%4];"
                 : "=r"(r[0]), "=r"(r[1]), "=r"(r[2]), "=r"(r[3]) : "r"(addr));
}
__device__ __forceinline__ void ldsm4t(uint32_t* r, uint32_t addr) {
    asm volatile("ldmatrix.sync.aligned.m8n8.x4.trans.shared.b16 {%0,%1,%2,%3}, [%4];"
                 : "=r"(r[0]), "=r"(r[1]), "=r"(r[2]), "=r"(r[3]) : "r"(addr));
}
__device__ __forceinline__ void mma_f16(float* d, const uint32_t* a, const uint32_t* b) {
    asm volatile(
        "mma.sync.aligned.m16n8k16.row.col.f32.f16.f16.f32 "
        "{%0,%1,%2,%3}, {%4,%5,%6,%7}, {%8,%9}, {%0,%1,%2,%3};"
        : "+f"(d[0]), "+f"(d[1]), "+f"(d[2]), "+f"(d[3])
        : "r"(a[0]), "r"(a[1]), "r"(a[2]), "r"(a[3]), "r"(b[0]), "r"(b[1]));
}
__device__ __forceinline__ void mbar_init(uint32_t m, uint32_t c) {
    asm volatile("mbarrier.init.shared.b64 [%0], %1;" :: "r"(m), "r"(c) : "memory");
}
__device__ __forceinline__ void mbar_arrive(uint32_t m) {
    asm volatile("mbarrier.arrive.shared.b64 _, [%0];" :: "r"(m) : "memory");
}
__device__ __forceinline__ void mbar_wait(uint32_t m, uint32_t parity) {
    uint32_t done;
    asm volatile(
        "{\n\t.reg .pred p;\n\t"
        "mbarrier.try_wait.parity.acquire.cta.shared::cta.b64 p, [%1], %2;\n\t"
        "selp.b32 %0, 1, 0, p;\n\t}"
        : "=r"(done) : "r"(m), "r"(parity) : "memory");
    if (!done) {
        asm volatile(
            "{\n\t.reg .pred P1;\n\t"
            "WL_%=:\n\t"
            "mbarrier.try_wait.parity.acquire.cta.shared::cta.b64 P1, [%0], %1, 0x989680;\n\t"
            "@P1 bra.uni WD_%=;\n\t"
            "bra.uni WL_%=;\n\t"
            "WD_%=:\n\t}"
            :: "r"(m), "r"(parity) : "memory");
    }
}
__device__ __forceinline__ void cp_async16(uint32_t dst, const void* src) {
    asm volatile("cp.async.cg.shared.global [%0], [%1], 16;"
                 :: "r"(dst), "l"(src) : "memory");
}

// ============ A prepass: fp32 -> fp16 ============
__global__ void __launch_bounds__(256) cvtA_kernel(const float* __restrict__ A) {
    const size_t base = ((size_t)blockIdx.x * 256 + threadIdx.x) * 8;
    const float4 v0 = *reinterpret_cast<const float4*>(A + base);
    const float4 v1 = *reinterpret_cast<const float4*>(A + base + 4);
    __half2 h0 = __floats2half2_rn(v0.x, v0.y);
    __half2 h1 = __floats2half2_rn(v0.z, v0.w);
    __half2 h2 = __floats2half2_rn(v1.x, v1.y);
    __half2 h3 = __floats2half2_rn(v1.z, v1.w);
    *reinterpret_cast<uint4*>(AhG + base) =
        make_uint4(*(uint32_t*)&h0, *(uint32_t*)&h1, *(uint32_t*)&h2, *(uint32_t*)&h3);
}

// ============ warp-specialized fused GEMM ============
__global__ void __launch_bounds__(THREADS, 1) gemm_f16_kernel(
    const unsigned* __restrict__ QW, const unsigned* __restrict__ QZ,
    const float* __restrict__ SC, float* __restrict__ C)
{
    extern __shared__ char smem[];
    const uint32_t sbase = smem_u32(smem);
    const int tid  = threadIdx.x;
    const int wid  = tid >> 5;
    const int lane = tid & 31;
    const int bm = blockIdx.y * BM;
    const int bn = blockIdx.x * BN;
    __half* scS = (__half*)(smem + OFF_SC);

    if (tid == 0) {
        #pragma unroll
        for (int s = 0; s < NSTAGE; s++) {
            mbar_init(sbase + OFF_BAR + 16 * s, 128);      // full: producer threads
            mbar_init(sbase + OFF_BAR + 16 * s + 8, 128);  // empty: consumer threads
        }
    }
    // stage scales as fp16 (32 groups x 128 n)
    for (int idx = tid; idx < 1024; idx += THREADS) {
        const int g = idx >> 5, v = idx & 31;
        const float4 s4 = *reinterpret_cast<const float4*>(
            SC + (size_t)g * N_TOT + bn + v * 4);
        __half2 a = __floats2half2_rn(s4.x, s4.y);
        __half2 b = __floats2half2_rn(s4.z, s4.w);
        *reinterpret_cast<uint2*>(scS + g * 128 + v * 4) =
            make_uint2(*(uint32_t*)&a, *(uint32_t*)&b);
    }
    __syncthreads();

    if (wid >= 4) {
        // ========== PRODUCER (warps 4-7, 128 threads) ==========
        const int ptid = tid - 128;
        const int bw  = ptid & 15;     // B n-octet / packed-word
        const int bkb = ptid >> 4;     // B k base 0..7 (+8*r)
        int pe[NSTAGE] = {1, 1, 1, 1, 1};

        for (int it = 0; it < NCH; ++it) {
            const int s = it % NSTAGE;
            mbar_wait(sbase + OFF_BAR + 16 * s + 8, pe[s]);
            pe[s] ^= 1;
            const int k0 = it * BK;
            char* stg = smem + OFF_STG + s * STG_BYTES;
            const uint32_t stgu = sbase + OFF_STG + s * STG_BYTES;

            // ---- A: cp.async fp16 straight into swizzled slots ----
            #pragma unroll
            for (int r = 0; r < 8; r++) {
                const int idx = ptid + r * 128;     // 0..1023
                const int m = idx >> 3, c = idx & 7;
                const __half* src = AhG + (size_t)(bm + m) * K_TOT + k0 + c * 8;
                const uint32_t dst = stgu + OFF_A + m * 128 + ((c ^ (m & 7)) << 4);
                cp_async16(dst, src);
            }
            asm volatile("cp.async.commit_group;" ::: "memory");

            // ---- B: q = nib - zp exact (bias 0x6400), then * s_fp16 ----
            const unsigned qz = QZ[(size_t)(it >> 1) * QWC + (bn >> 3) + bw];
            unsigned qw[8];
            #pragma unroll
            for (int r = 0; r < 8; r++)
                qw[r] = QW[(size_t)(k0 + bkb + 8 * r) * QWC + (bn >> 3) + bw];
            uint32_t zz[4];
            #pragma unroll
            for (int p = 0; p < 4; p++) {
                const unsigned zq = qz >> (8 * p);
                zz[p] = BIAS2 | (zq & 0xFu) | ((zq & 0xF0u) << 12);
            }
            // scales for this n-octet (group of current k-chunk)
            uint4 sv = *reinterpret_cast<const uint4*>(
                scS + (size_t)(it >> 1) * 128 + bw * 8);
            const uint32_t sc2[4] = {sv.x, sv.y, sv.z, sv.w};
            #pragma unroll
            for (int r = 0; r < 8; r++) {
                const int k = bkb + 8 * r;
                const unsigned q = qw[r];
                uint32_t w[4];
                #pragma unroll
                for (int p = 0; p < 4; p++) {
                    const unsigned qq = q >> (8 * p);
                    uint32_t u = BIAS2 | (qq & 0xFu) | ((qq & 0xF0u) << 12);
                    __half2 d = __hsub2(*reinterpret_cast<__half2*>(&u),
                                        *reinterpret_cast<__half2*>(&zz[p]));
                    __half2 b = __hmul2(d, *reinterpret_cast<const __half2*>(&sc2[p]));
                    w[p] = *reinterpret_cast<uint32_t*>(&b);
                }
                const int off = k * 256 + ((bw ^ (k & 7)) << 4);
                *reinterpret_cast<uint4*>(stg + OFF_B + off) =
                    make_uint4(w[0], w[1], w[2], w[3]);
            }
            asm volatile("cp.async.wait_group 0;" ::: "memory");
            mbar_arrive(sbase + OFF_BAR + 16 * s);   // full
        }
    } else {
        // ========== CONSUMER (warps 0-3, 128 threads), 64x64 warp tiles ==========
        const int wm = (wid & 1) * 64;
        const int wn = (wid >> 1) * 64;
        const int rsel = ((lane >> 3) & 1) * 8 + (lane & 7);
        const int hi8  = lane >> 4;
        const int l7   = lane & 7;
        int cf[NSTAGE] = {0, 0, 0, 0, 0};

        float accF[4][8][4];
        #pragma unroll
        for (int i = 0; i < 4; i++)
            #pragma unroll
            for (int j = 0; j < 8; j++)
                #pragma unroll
                for (int e = 0; e < 4; e++) accF[i][j][e] = 0.f;

        for (int it = 0; it < NCH; ++it) {
            const int s = it % NSTAGE;
            mbar_wait(sbase + OFF_BAR + 16 * s, cf[s]);
            cf[s] ^= 1;

            const uint32_t base = sbase + OFF_STG + s * STG_BYTES;
            #pragma unroll
            for (int ks = 0; ks < 4; ks++) {
                uint32_t bq[8][2];
                const int krow = ks * 16 + rsel;
                #pragma unroll
                for (int pr = 0; pr < 4; pr++) {
                    const int ch = (wn >> 3) + pr * 2 + hi8;
                    const int off = krow * 256 + ((ch ^ l7) << 4);
                    uint32_t t[4];
                    ldsm4t(t, base + OFF_B + off);
                    bq[pr*2][0]=t[0]; bq[pr*2][1]=t[1];
                    bq[pr*2+1][0]=t[2]; bq[pr*2+1][1]=t[3];
                }
                #pragma unroll
                for (int mi = 0; mi < 4; mi++) {
                    const int m = wm + mi * 16 + rsel;
                    const int aoff = m * 128 + (((ks * 2 + hi8) ^ l7) << 4);
                    uint32_t a[4];
                    ldsm4(a, base + OFF_A + aoff);
                    #pragma unroll
                    for (int nj = 0; nj < 8; nj++) mma_f16(accF[mi][nj], a, bq[nj]);
                }
            }
            mbar_arrive(sbase + OFF_BAR + 16 * s + 8);   // empty
        }

        // epilogue
        #pragma unroll
        for (int mi = 0; mi < 4; mi++)
            #pragma unroll
            for (int nj = 0; nj < 8; nj++) {
                const float* a = accF[mi][nj];
                const int row = bm + wm + mi * 16 + (lane >> 2);
                const int col = bn + wn + nj * 8 + (lane & 3) * 2;
                *reinterpret_cast<float2*>(&C[(size_t)row * N_TOT + col]) =
                    make_float2(a[0], a[1]);
                *reinterpret_cast<float2*>(&C[(size_t)(row + 8) * N_TOT + col]) =
                    make_float2(a[2], a[3]);
            }
    }
}

extern "C" void kernel_launch(void* const* d_in, const int* in_sizes, int n_in,
                              void* d_out, int out_size)
{
    const float*    A  = (const float*)d_in[0];
    const unsigned* QW = (const unsigned*)d_in[1];
    const unsigned* QZ = (const unsigned*)d_in[2];
    const float*    SC = (const float*)d_in[3];
    float*          C  = (float*)d_out;

    cvtA_kernel<<<(M_TOT * K_TOT) / (256 * 8), 256>>>(A);

    cudaFuncSetAttribute(gemm_f16_kernel,
                         cudaFuncAttributeMaxDynamicSharedMemorySize, SMEM_TOTAL);
    dim3 grid(N_TOT / BN, M_TOT / BM);   // (86, 32)
    gemm_f16_kernel<<<grid, THREADS, SMEM_TOTAL>>>(QW, QZ, SC, C);
}